// round 8
// baseline (speedup 1.0000x reference)
#include <cuda_runtime.h>
#include <cuda_bf16.h>
#include <cstdint>

#define BATCH 8
#define SEQ   2048
#define CDIM  1024
#define HDIM  64
#define BT    (BATCH*SEQ)

// bf16 planes (packed u32 pairs), written by proj, read by attn
__device__ uint32_t g_qh[BT*32], g_ql[BT*32];      // q pre-scaled by 1/32, hi/lo
__device__ uint32_t g_kh[BT*32];                   // k hi only (2-term S)
__device__ uint32_t g_vh[BT*32], g_vl[BT*32];      // v hi/lo
__device__ __nv_bfloat16 g_wh[CDIM*192];           // [k][n0..191] = Wk|Wq|Wv hi
__device__ __nv_bfloat16 g_wvl[CDIM*64];           // Wv lo

// ---------------- helpers ----------------
__device__ __forceinline__ uint32_t smem_u32(const void* p){
    uint32_t a; asm("{ .reg .u64 t; cvta.to.shared.u64 t, %1; cvt.u32.u64 %0, t; }" : "=r"(a) : "l"(p)); return a;
}
__device__ __forceinline__ void ldm4(uint32_t* r, uint32_t a){
    asm volatile("ldmatrix.sync.aligned.m8n8.x4.shared.b16 {%0,%1,%2,%3},[%4];"
        : "=r"(r[0]),"=r"(r[1]),"=r"(r[2]),"=r"(r[3]) : "r"(a));
}
__device__ __forceinline__ void ldm4t(uint32_t* r, uint32_t a){
    asm volatile("ldmatrix.sync.aligned.m8n8.x4.trans.shared.b16 {%0,%1,%2,%3},[%4];"
        : "=r"(r[0]),"=r"(r[1]),"=r"(r[2]),"=r"(r[3]) : "r"(a));
}
__device__ __forceinline__ void mma16816(float* d, const uint32_t* a, const uint32_t* b){
    asm volatile("mma.sync.aligned.m16n8k16.row.col.f32.bf16.bf16.f32 "
        "{%0,%1,%2,%3},{%4,%5,%6,%7},{%8,%9},{%0,%1,%2,%3};"
        : "+f"(d[0]),"+f"(d[1]),"+f"(d[2]),"+f"(d[3])
        : "r"(a[0]),"r"(a[1]),"r"(a[2]),"r"(a[3]),"r"(b[0]),"r"(b[1]));
}
__device__ __forceinline__ uint32_t pkh(__nv_bfloat16 x, __nv_bfloat16 y){
    __nv_bfloat162 t = __halves2bfloat162(x, y); return *(uint32_t*)&t;
}
__device__ __forceinline__ uint32_t pk2(float x, float y){
    return pkh(__float2bfloat16(x), __float2bfloat16(y));
}
__device__ __forceinline__ void split_store(char* hp, char* lp, float4 v){
    __nv_bfloat16 hx=__float2bfloat16(v.x), hy=__float2bfloat16(v.y);
    __nv_bfloat16 hz=__float2bfloat16(v.z), hw=__float2bfloat16(v.w);
    uint2 h, l;
    h.x = pkh(hx,hy); h.y = pkh(hz,hw);
    l.x = pk2(v.x-__bfloat162float(hx), v.y-__bfloat162float(hy));
    l.y = pk2(v.z-__bfloat162float(hz), v.w-__bfloat162float(hw));
    *(uint2*)hp = h; *(uint2*)lp = l;
}
__device__ __forceinline__ void wr2(uint32_t* ph, uint32_t* pl, int r, int c, float a, float b){
    __nv_bfloat16 h0=__float2bfloat16(a), h1=__float2bfloat16(b);
    size_t idx = (size_t)r*32 + (c>>1);
    ph[idx] = pkh(h0,h1);
    pl[idx] = pk2(a-__bfloat162float(h0), b-__bfloat162float(h1));
}
__device__ __forceinline__ uint32_t aA(uint32_t base, int lane, int SB){
    return base + (uint32_t)((lane&15)*SB + (lane>>4)*16);
}
__device__ __forceinline__ uint32_t aB(uint32_t base, int lane, int SB){
    return base + (uint32_t)(((((lane>>4)&1)<<3) + (lane&7))*SB + ((lane>>3)&1)*16);
}

// ---------------- kernel 0: W hi/lo pre-split (coalesced, 96 blocks) ----------------
__global__ void wsplit(const float* __restrict__ Wk, const float* __restrict__ Wq,
                       const float* __restrict__ Wv){
    int idx0 = blockIdx.x*2048 + threadIdx.x;
    #pragma unroll
    for (int i=0;i<8;++i){
        int idx = idx0 + i*256;         // k-major over [1024][192]
        int k = idx/192, n = idx - k*192;
        int m = n>>6, c = n&63;
        const float* W = (m==0)?Wk:(m==1)?Wq:Wv;
        float v = W[(size_t)k*HDIM + c];
        __nv_bfloat16 h = __float2bfloat16(v);
        g_wh[(size_t)k*192 + n] = h;
        if (m==2) g_wvl[(size_t)k*HDIM + c] = __float2bfloat16(v - __bfloat162float(h));
    }
}

// ---------------- kernel 1: fused QKV projection (double-buffered) ----------------
// 512 thr, 16 warps (wm 0..3 x wn 0..3). M=128 rows, N=192. K chunks of 64.
// k,q: 2-term (xh*Wh + xl*Wh). v: 3-term (+ xh*Wvl). 1 sync per chunk.
#define PBUF 70656          // XH 0 | XL 18432 | B 36864 (stride 528, 33792B)
#define PJ_SMEM 141312
__global__ __launch_bounds__(512,1) void proj_mma(const float* __restrict__ x){
    extern __shared__ char sm[];
    const uint32_t sb = smem_u32(sm);
    const int tid=threadIdx.x, lane=tid&31, wid=tid>>5;
    const int wm=wid>>2, wn=wid&3, g=lane>>2, tig=lane&3;
    const int m0 = blockIdx.x*128;

    float4 xr[4]; uint4 br[4];
    #pragma unroll
    for (int i=0;i<4;++i){ int lin=tid+i*512, row=lin>>4, c4=(lin&15)*4;
        xr[i] = *(const float4*)(x + (size_t)(m0+row)*CDIM + c4); }
    #pragma unroll
    for (int i=0;i<4;++i){ int lin=tid+i*512, row=lin>>5, c8=(lin&31)*8;
        br[i] = (c8<192) ? *(const uint4*)(g_wh + (size_t)row*192 + c8)
                         : *(const uint4*)(g_wvl + (size_t)row*64 + (c8-192)); }
    #pragma unroll
    for (int i=0;i<4;++i){ int lin=tid+i*512, row=lin>>4, c4=(lin&15)*4;
        split_store(sm + row*144 + c4*2, sm + 18432 + row*144 + c4*2, xr[i]); }
    #pragma unroll
    for (int i=0;i<4;++i){ int lin=tid+i*512, row=lin>>5, c8=(lin&31)*8;
        *(uint4*)(sm + 36864 + row*528 + c8*2) = br[i]; }
    __syncthreads();

    float acc[2][3][2][4] = {};
    for (int c=0;c<16;++c){
        uint32_t pbu = sb + (c&1)*PBUF;
        if (c<15){
            #pragma unroll
            for (int i=0;i<4;++i){ int lin=tid+i*512, row=lin>>4, c4=(lin&15)*4;
                xr[i] = *(const float4*)(x + (size_t)(m0+row)*CDIM + (c+1)*64 + c4); }
            #pragma unroll
            for (int i=0;i<4;++i){ int lin=tid+i*512, row=lin>>5, c8=(lin&31)*8;
                br[i] = (c8<192) ? *(const uint4*)(g_wh + (size_t)((c+1)*64+row)*192 + c8)
                                 : *(const uint4*)(g_wvl + (size_t)((c+1)*64+row)*64 + (c8-192)); }
        }
        #pragma unroll
        for (int ks=0;ks<4;++ks){
            int k0 = ks*16;
            uint32_t ah[2][4], al[2][4];
            #pragma unroll
            for (int mi=0;mi<2;++mi){
                uint32_t base = pbu + (wm*32+mi*16)*144 + k0*2;
                ldm4(ah[mi], aA(base,lane,144));
                ldm4(al[mi], aA(base+18432,lane,144));
            }
            #pragma unroll
            for (int nt=0;nt<3;++nt){
                int tt = wn + nt*4;
                uint32_t bh[4], bl[4];
                uint32_t bb = pbu + 36864 + k0*528;
                ldm4t(bh, aA(bb + tt*32, lane, 528));
                if (nt==2) ldm4t(bl, aA(bb + 384 + wn*32, lane, 528));
                #pragma unroll
                for (int mi=0;mi<2;++mi)
                    #pragma unroll
                    for (int n8=0;n8<2;++n8){
                        mma16816(acc[mi][nt][n8], ah[mi], bh+n8*2);
                        mma16816(acc[mi][nt][n8], al[mi], bh+n8*2);
                        if (nt==2) mma16816(acc[mi][nt][n8], ah[mi], bl+n8*2);
                    }
            }
        }
        if (c<15){
            char* nb = sm + ((c+1)&1)*PBUF;
            #pragma unroll
            for (int i=0;i<4;++i){ int lin=tid+i*512, row=lin>>4, c4=(lin&15)*4;
                split_store(nb + row*144 + c4*2, nb + 18432 + row*144 + c4*2, xr[i]); }
            #pragma unroll
            for (int i=0;i<4;++i){ int lin=tid+i*512, row=lin>>5, c8=(lin&31)*8;
                *(uint4*)(nb + 36864 + row*528 + c8*2) = br[i]; }
        }
        __syncthreads();
    }
    #pragma unroll
    for (int mi=0;mi<2;++mi)
        #pragma unroll
        for (int nt=0;nt<3;++nt)
            #pragma unroll
            for (int n8=0;n8<2;++n8){
                int ncol = (wn+nt*4)*16 + n8*8 + tig*2;
                int cc = ncol&63;
                int r0 = m0 + wm*32 + mi*16 + g;
                float* a = acc[mi][nt][n8];
                if (nt==0){
                    g_kh[((size_t)r0*64+cc)>>1]     = pk2(a[0],a[1]);
                    g_kh[((size_t)(r0+8)*64+cc)>>1] = pk2(a[2],a[3]);
                } else if (nt==1){
                    wr2(g_qh,g_ql,r0,  cc, a[0]*0.03125f, a[1]*0.03125f);
                    wr2(g_qh,g_ql,r0+8,cc, a[2]*0.03125f, a[3]*0.03125f);
                } else {
                    wr2(g_vh,g_vl,r0,  cc, a[0], a[1]);
                    wr2(g_vh,g_vl,r0+8,cc, a[2], a[3]);
                }
            }
}

// ---------------- kernel 2: attention (double-buffered KV, P hi/lo) ----------------
// 512 thr. S: 2-term (Qh+Ql)*Kh. PV: 3-term Ph*Vh + Pl*Vh + Ph*Vl. 2 syncs/iter.
#define AQH 0
#define AQL 18432
#define AKV0 36864           // per buffer: K +0 | VH +18432 | VL +36864 (55296 B)
#define AKVSZ 55296
#define APH 147456           // 128 x 272B
#define APL 182272           // 128 x 272B
#define ALR 217088
#define AT_SMEM 219136
__global__ __launch_bounds__(512,1) void attn_mma(float* __restrict__ out){
    extern __shared__ char sm[];
    const uint32_t sb = smem_u32(sm);
    const int tid=threadIdx.x, lane=tid&31, wid=tid>>5;
    const int wm=wid>>2, wn=wid&3, g=lane>>2, tig=lane&3;
    const int b=blockIdx.y, q0=blockIdx.x*128;

    // stage Q (pre-scaled, pre-split by proj)
    #pragma unroll
    for (int i=0;i<4;++i){
        int lin=tid+i*512, plane=lin>>10, rem=lin&1023, row=rem>>3, c8h=(rem&7)*4;
        const uint32_t* src = (plane? g_ql : g_qh) + ((size_t)(b*SEQ+q0)+row)*32 + c8h;
        *(uint4*)(sm + (plane?AQL:AQH) + row*144 + c8h*4) = *(const uint4*)src;
    }
    // load + stage KV tile 0 into buf0
    uint4 kv[6];
    #pragma unroll
    for (int i=0;i<6;++i){
        int lin=tid+i*512, plane=lin>>10, rem=lin&1023, row=rem>>3, c8h=(rem&7)*4;
        const uint32_t* gp = plane==0?g_kh:plane==1?g_vh:g_vl;
        kv[i] = *(const uint4*)(gp + ((size_t)(b*SEQ)+row)*32 + c8h);
    }
    #pragma unroll
    for (int i=0;i<6;++i){
        int lin=tid+i*512, plane=lin>>10, rem=lin&1023, row=rem>>3, c8h=(rem&7)*4;
        *(uint4*)(sm + AKV0 + plane*18432 + row*144 + c8h*4) = kv[i];
    }
    __syncthreads();

    float oacc[2][2][4] = {};
    float lsum[4] = {};
    for (int t=0;t<16;++t){
        uint32_t kvb = sb + AKV0 + (t&1)*AKVSZ;
        if (t<15){
            #pragma unroll
            for (int i=0;i<6;++i){
                int lin=tid+i*512, plane=lin>>10, rem=lin&1023, row=rem>>3, c8h=(rem&7)*4;
                const uint32_t* gp = plane==0?g_kh:plane==1?g_vh:g_vl;
                kv[i] = *(const uint4*)(gp + ((size_t)(b*SEQ)+(t+1)*128+row)*32 + c8h);
            }
        }
        // ---- S = Q K^T (2-term) ----
        float sacc[2][4][4] = {};
        #pragma unroll
        for (int ks=0;ks<4;++ks){
            int k0=ks*16;
            uint32_t qh[2][4], ql[2][4];
            #pragma unroll
            for (int mi=0;mi<2;++mi){
                uint32_t base = sb + AQH + (wm*32+mi*16)*144 + k0*2;
                ldm4(qh[mi], aA(base,lane,144));
                ldm4(ql[mi], aA(base+(AQL-AQH),lane,144));
            }
            #pragma unroll
            for (int nt=0;nt<2;++nt){
                uint32_t kf[4];
                ldm4(kf, aB(kvb + (wn*32+nt*16)*144 + k0*2, lane, 144));
                #pragma unroll
                for (int mi=0;mi<2;++mi)
                    #pragma unroll
                    for (int n8=0;n8<2;++n8){
                        mma16816(sacc[mi][nt*2+n8], qh[mi], kf+n8*2);
                        mma16816(sacc[mi][nt*2+n8], ql[mi], kf+n8*2);
                    }
            }
        }
        // ---- exp + P (hi/lo) ----
        #pragma unroll
        for (int mi=0;mi<2;++mi)
            #pragma unroll
            for (int j=0;j<4;++j){
                float p0=__expf(sacc[mi][j][0]), p1=__expf(sacc[mi][j][1]);
                float p2=__expf(sacc[mi][j][2]), p3=__expf(sacc[mi][j][3]);
                lsum[mi*2] += p0+p1; lsum[mi*2+1] += p2+p3;
                int col = wn*32 + (j>>1)*16 + (j&1)*8 + tig*2;
                int row = wm*32 + mi*16 + g;
                __nv_bfloat16 h0=__float2bfloat16(p0), h1=__float2bfloat16(p1);
                __nv_bfloat16 h2=__float2bfloat16(p2), h3=__float2bfloat16(p3);
                *(uint32_t*)(sm+APH+row*272+col*2) = pkh(h0,h1);
                *(uint32_t*)(sm+APL+row*272+col*2) = pk2(p0-__bfloat162float(h0), p1-__bfloat162float(h1));
                *(uint32_t*)(sm+APH+(row+8)*272+col*2) = pkh(h2,h3);
                *(uint32_t*)(sm+APL+(row+8)*272+col*2) = pk2(p2-__bfloat162float(h2), p3-__bfloat162float(h3));
            }
        __syncthreads();
        // ---- O += (Ph+Pl) Vh + Ph Vl ----
        #pragma unroll
        for (int ks=0;ks<8;++ks){
            int k0=ks*16;
            uint32_t ph[2][4], pl[2][4], vh[4], vl[4];
            #pragma unroll
            for (int mi=0;mi<2;++mi){
                uint32_t base = sb + APH + (wm*32+mi*16)*272 + k0*2;
                ldm4(ph[mi], aA(base,lane,272));
                ldm4(pl[mi], aA(base+(APL-APH),lane,272));
            }
            uint32_t vb = kvb + 18432 + k0*144 + wn*32;
            ldm4t(vh, aA(vb,lane,144));
            ldm4t(vl, aA(vb+18432,lane,144));
            #pragma unroll
            for (int mi=0;mi<2;++mi)
                #pragma unroll
                for (int n8=0;n8<2;++n8){
                    mma16816(oacc[mi][n8], ph[mi], vh+n8*2);
                    mma16816(oacc[mi][n8], pl[mi], vh+n8*2);
                    mma16816(oacc[mi][n8], ph[mi], vl+n8*2);
                }
        }
        if (t<15){
            char* nb = sm + AKV0 + ((t+1)&1)*AKVSZ;
            #pragma unroll
            for (int i=0;i<6;++i){
                int lin=tid+i*512, plane=lin>>10, rem=lin&1023, row=rem>>3, c8h=(rem&7)*4;
                *(uint4*)(nb + plane*18432 + row*144 + c8h*4) = kv[i];
            }
        }
        __syncthreads();
    }
    // ---- row-sum reduction: tig lanes, then across the 4 wn warps ----
    #pragma unroll
    for (int i=0;i<4;++i){
        lsum[i] += __shfl_xor_sync(0xffffffffu, lsum[i], 1);
        lsum[i] += __shfl_xor_sync(0xffffffffu, lsum[i], 2);
    }
    float* lred = (float*)(sm + ALR);
    if (tig==0){
        #pragma unroll
        for (int i=0;i<4;++i){
            int row = wm*32 + (i>>1)*16 + (i&1)*8 + g;
            lred[wn*128 + row] = lsum[i];
        }
    }
    __syncthreads();
    float inv[4];
    #pragma unroll
    for (int i=0;i<4;++i){
        int row = wm*32 + (i>>1)*16 + (i&1)*8 + g;
        inv[i] = 1.f/(lred[row] + lred[128+row] + lred[256+row] + lred[384+row]);
    }
    float* og = out + ((size_t)b*SEQ + q0)*HDIM;
    #pragma unroll
    for (int mi=0;mi<2;++mi)
        #pragma unroll
        for (int n8=0;n8<2;++n8){
            int col = wn*16 + n8*8 + tig*2;
            int r = wm*32 + mi*16 + g;
            *(float2*)(og + (size_t)r*HDIM + col) =
                make_float2(oacc[mi][n8][0]*inv[mi*2], oacc[mi][n8][1]*inv[mi*2]);
            *(float2*)(og + (size_t)(r+8)*HDIM + col) =
                make_float2(oacc[mi][n8][2]*inv[mi*2+1], oacc[mi][n8][3]*inv[mi*2+1]);
        }
}

extern "C" void kernel_launch(void* const* d_in, const int* in_sizes, int n_in,
                              void* d_out, int out_size)
{
    const float* x  = (const float*)d_in[0];
    const float* Wk = (const float*)d_in[1];
    const float* Wq = (const float*)d_in[2];
    const float* Wv = (const float*)d_in[3];
    float* out = (float*)d_out;

    cudaFuncSetAttribute(proj_mma, cudaFuncAttributeMaxDynamicSharedMemorySize, PJ_SMEM);
    cudaFuncSetAttribute(attn_mma, cudaFuncAttributeMaxDynamicSharedMemorySize, AT_SMEM);

    wsplit<<<96, 256>>>(Wk, Wq, Wv);
    proj_mma<<<BT/128, 512, PJ_SMEM>>>(x);
    attn_mma<<<dim3(SEQ/128, BATCH), 512, AT_SMEM>>>(out);
}

// round 9
// speedup vs baseline: 1.1891x; 1.1891x over previous
#include <cuda_runtime.h>
#include <cuda_fp16.h>
#include <cstdint>

#define BATCH 8
#define SEQ   2048
#define CDIM  1024
#define HDIM  64
#define BT    (BATCH*SEQ)

// fp16 planes (packed u32 pairs), written by proj, read by attn
__device__ uint32_t g_qh[BT*32], g_ql[BT*32];      // q pre-scaled by 1/32, hi/lo
__device__ uint32_t g_kh[BT*32];                   // k hi only
__device__ uint32_t g_vh[BT*32], g_vl[BT*32];      // v hi/lo

// ---------------- helpers ----------------
__device__ __forceinline__ uint32_t smem_u32(const void* p){
    uint32_t a; asm("{ .reg .u64 t; cvta.to.shared.u64 t, %1; cvt.u32.u64 %0, t; }" : "=r"(a) : "l"(p)); return a;
}
__device__ __forceinline__ void ldm4(uint32_t* r, uint32_t a){
    asm volatile("ldmatrix.sync.aligned.m8n8.x4.shared.b16 {%0,%1,%2,%3},[%4];"
        : "=r"(r[0]),"=r"(r[1]),"=r"(r[2]),"=r"(r[3]) : "r"(a));
}
__device__ __forceinline__ void ldm4t(uint32_t* r, uint32_t a){
    asm volatile("ldmatrix.sync.aligned.m8n8.x4.trans.shared.b16 {%0,%1,%2,%3},[%4];"
        : "=r"(r[0]),"=r"(r[1]),"=r"(r[2]),"=r"(r[3]) : "r"(a));
}
__device__ __forceinline__ void mma16816(float* d, const uint32_t* a, const uint32_t* b){
    asm volatile("mma.sync.aligned.m16n8k16.row.col.f32.f16.f16.f32 "
        "{%0,%1,%2,%3},{%4,%5,%6,%7},{%8,%9},{%0,%1,%2,%3};"
        : "+f"(d[0]),"+f"(d[1]),"+f"(d[2]),"+f"(d[3])
        : "r"(a[0]),"r"(a[1]),"r"(a[2]),"r"(a[3]),"r"(b[0]),"r"(b[1]));
}
__device__ __forceinline__ uint32_t pk2(float x, float y){     // 2x f32 -> packed f16x2
    __half2 t = __floats2half2_rn(x, y); return *(uint32_t*)&t;
}
__device__ __forceinline__ uint32_t pkh(__half x, __half y){
    __half2 t = __halves2half2(x, y); return *(uint32_t*)&t;
}
__device__ __forceinline__ void split_store(char* hp, char* lp, float4 v){
    __half hx=__float2half_rn(v.x), hy=__float2half_rn(v.y);
    __half hz=__float2half_rn(v.z), hw=__float2half_rn(v.w);
    uint2 h, l;
    h.x = pkh(hx,hy); h.y = pkh(hz,hw);
    l.x = pk2(v.x-__half2float(hx), v.y-__half2float(hy));
    l.y = pk2(v.z-__half2float(hz), v.w-__half2float(hw));
    *(uint2*)hp = h; *(uint2*)lp = l;
}
__device__ __forceinline__ void wr2(uint32_t* ph, uint32_t* pl, int r, int c, float a, float b){
    __half h0=__float2half_rn(a), h1=__float2half_rn(b);
    size_t idx = (size_t)r*32 + (c>>1);
    ph[idx] = pkh(h0,h1);
    pl[idx] = pk2(a-__half2float(h0), b-__half2float(h1));
}
__device__ __forceinline__ uint32_t aA(uint32_t base, int lane, int SB){
    return base + (uint32_t)((lane&15)*SB + (lane>>4)*16);
}
__device__ __forceinline__ uint32_t aB(uint32_t base, int lane, int SB){
    return base + (uint32_t)(((((lane>>4)&1)<<3) + (lane&7))*SB + ((lane>>3)&1)*16);
}

// ---------------- kernel 1: fused QKV projection (double-buffered, in-CTA W convert) ----
// 512 thr, 16 warps (wm 0..3 x wn 0..3). M=128 rows, N=192. K chunks of 64.
// All outputs 2-term: xh*Wh + xl*Wh (W hi-only fp16).
#define PXH 0
#define PXL 18432
#define PB  36864            // 64 rows x 400B (192 f16 + pad)
#define PBUF 62464
#define PJ_SMEM 124928
__global__ __launch_bounds__(512,1) void proj_mma(
    const float* __restrict__ x, const float* __restrict__ Wk,
    const float* __restrict__ Wq, const float* __restrict__ Wv)
{
    extern __shared__ char sm[];
    const uint32_t sb = smem_u32(sm);
    const int tid=threadIdx.x, lane=tid&31, wid=tid>>5;
    const int wm=wid>>2, wn=wid&3, g=lane>>2, tig=lane&3;
    const int m0 = blockIdx.x*128;
    const float* Ws[3] = {Wk, Wq, Wv};

    float4 xr[4], wr[6];
    #pragma unroll
    for (int i=0;i<4;++i){ int lin=tid+i*512, row=lin>>4, c4=(lin&15)*4;
        xr[i] = *(const float4*)(x + (size_t)(m0+row)*CDIM + c4); }
    #pragma unroll
    for (int i=0;i<6;++i){ int lin=tid+i*512, row=lin/48, c4=(lin-row*48)*4;
        wr[i] = *(const float4*)(Ws[c4>>6] + (size_t)row*HDIM + (c4&63)); }
    #pragma unroll
    for (int i=0;i<4;++i){ int lin=tid+i*512, row=lin>>4, c4=(lin&15)*4;
        split_store(sm + PXH + row*144 + c4*2, sm + PXL + row*144 + c4*2, xr[i]); }
    #pragma unroll
    for (int i=0;i<6;++i){ int lin=tid+i*512, row=lin/48, c4=(lin-row*48)*4;
        *(uint2*)(sm + PB + row*400 + c4*2) =
            make_uint2(pk2(wr[i].x,wr[i].y), pk2(wr[i].z,wr[i].w)); }
    __syncthreads();

    float acc[2][3][2][4] = {};
    for (int c=0;c<16;++c){
        uint32_t pbu = sb + (c&1)*PBUF;
        if (c<15){
            #pragma unroll
            for (int i=0;i<4;++i){ int lin=tid+i*512, row=lin>>4, c4=(lin&15)*4;
                xr[i] = *(const float4*)(x + (size_t)(m0+row)*CDIM + (c+1)*64 + c4); }
            #pragma unroll
            for (int i=0;i<6;++i){ int lin=tid+i*512, row=lin/48, c4=(lin-row*48)*4;
                wr[i] = *(const float4*)(Ws[c4>>6] + (size_t)((c+1)*64+row)*HDIM + (c4&63)); }
        }
        #pragma unroll
        for (int ks=0;ks<4;++ks){
            int k0 = ks*16;
            uint32_t ah[2][4], al[2][4];
            #pragma unroll
            for (int mi=0;mi<2;++mi){
                uint32_t base = pbu + PXH + (wm*32+mi*16)*144 + k0*2;
                ldm4(ah[mi], aA(base,lane,144));
                ldm4(al[mi], aA(base+(PXL-PXH),lane,144));
            }
            #pragma unroll
            for (int nt=0;nt<3;++nt){
                int tt = wn + nt*4;
                uint32_t bh[4];
                ldm4t(bh, aA(pbu + PB + k0*400 + tt*32, lane, 400));
                #pragma unroll
                for (int mi=0;mi<2;++mi)
                    #pragma unroll
                    for (int n8=0;n8<2;++n8){
                        mma16816(acc[mi][nt][n8], ah[mi], bh+n8*2);
                        mma16816(acc[mi][nt][n8], al[mi], bh+n8*2);
                    }
            }
        }
        if (c<15){
            char* nb = sm + ((c+1)&1)*PBUF;
            #pragma unroll
            for (int i=0;i<4;++i){ int lin=tid+i*512, row=lin>>4, c4=(lin&15)*4;
                split_store(nb + PXH + row*144 + c4*2, nb + PXL + row*144 + c4*2, xr[i]); }
            #pragma unroll
            for (int i=0;i<6;++i){ int lin=tid+i*512, row=lin/48, c4=(lin-row*48)*4;
                *(uint2*)(nb + PB + row*400 + c4*2) =
                    make_uint2(pk2(wr[i].x,wr[i].y), pk2(wr[i].z,wr[i].w)); }
        }
        __syncthreads();
    }
    #pragma unroll
    for (int mi=0;mi<2;++mi)
        #pragma unroll
        for (int nt=0;nt<3;++nt)
            #pragma unroll
            for (int n8=0;n8<2;++n8){
                int ncol = (wn+nt*4)*16 + n8*8 + tig*2;
                int cc = ncol&63;
                int r0 = m0 + wm*32 + mi*16 + g;
                float* a = acc[mi][nt][n8];
                if (nt==0){
                    g_kh[((size_t)r0*64+cc)>>1]     = pk2(a[0],a[1]);
                    g_kh[((size_t)(r0+8)*64+cc)>>1] = pk2(a[2],a[3]);
                } else if (nt==1){
                    wr2(g_qh,g_ql,r0,  cc, a[0]*0.03125f, a[1]*0.03125f);
                    wr2(g_qh,g_ql,r0+8,cc, a[2]*0.03125f, a[3]*0.03125f);
                } else {
                    wr2(g_vh,g_vl,r0,  cc, a[0], a[1]);
                    wr2(g_vh,g_vl,r0+8,cc, a[2], a[3]);
                }
            }
}

// ---------------- kernel 2: attention (double-buffered KV, P fp16 hi-only) ----------------
// 512 thr. S: 2-term (Qh+Ql)*Kh. PV: 2-term Ph*(Vh+Vl). 2 syncs/iter.
#define AQH 0
#define AQL 18432
#define AKV0 36864           // per buffer: K +0 | VH +18432 | VL +36864 (55296 B)
#define AKVSZ 55296
#define APH 147456           // 128 x 272B
#define ALR 182272
#define AT_SMEM 184320
__global__ __launch_bounds__(512,1) void attn_mma(float* __restrict__ out){
    extern __shared__ char sm[];
    const uint32_t sb = smem_u32(sm);
    const int tid=threadIdx.x, lane=tid&31, wid=tid>>5;
    const int wm=wid>>2, wn=wid&3, g=lane>>2, tig=lane&3;
    const int b=blockIdx.y, q0=blockIdx.x*128;

    // stage Q (pre-scaled, pre-split by proj)
    #pragma unroll
    for (int i=0;i<4;++i){
        int lin=tid+i*512, plane=lin>>10, rem=lin&1023, row=rem>>3, c8h=(rem&7)*4;
        const uint32_t* src = (plane? g_ql : g_qh) + ((size_t)(b*SEQ+q0)+row)*32 + c8h;
        *(uint4*)(sm + (plane?AQL:AQH) + row*144 + c8h*4) = *(const uint4*)src;
    }
    // load + stage KV tile 0 into buf0
    uint4 kv[6];
    #pragma unroll
    for (int i=0;i<6;++i){
        int lin=tid+i*512, plane=lin>>10, rem=lin&1023, row=rem>>3, c8h=(rem&7)*4;
        const uint32_t* gp = plane==0?g_kh:plane==1?g_vh:g_vl;
        kv[i] = *(const uint4*)(gp + ((size_t)(b*SEQ)+row)*32 + c8h);
    }
    #pragma unroll
    for (int i=0;i<6;++i){
        int lin=tid+i*512, plane=lin>>10, rem=lin&1023, row=rem>>3, c8h=(rem&7)*4;
        *(uint4*)(sm + AKV0 + plane*18432 + row*144 + c8h*4) = kv[i];
    }
    __syncthreads();

    float oacc[2][2][4] = {};
    float lsum[4] = {};
    for (int t=0;t<16;++t){
        uint32_t kvb = sb + AKV0 + (t&1)*AKVSZ;
        if (t<15){
            #pragma unroll
            for (int i=0;i<6;++i){
                int lin=tid+i*512, plane=lin>>10, rem=lin&1023, row=rem>>3, c8h=(rem&7)*4;
                const uint32_t* gp = plane==0?g_kh:plane==1?g_vh:g_vl;
                kv[i] = *(const uint4*)(gp + ((size_t)(b*SEQ)+(t+1)*128+row)*32 + c8h);
            }
        }
        // ---- S = Q K^T (2-term) ----
        float sacc[2][4][4] = {};
        #pragma unroll
        for (int ks=0;ks<4;++ks){
            int k0=ks*16;
            uint32_t qh[2][4], ql[2][4];
            #pragma unroll
            for (int mi=0;mi<2;++mi){
                uint32_t base = sb + AQH + (wm*32+mi*16)*144 + k0*2;
                ldm4(qh[mi], aA(base,lane,144));
                ldm4(ql[mi], aA(base+(AQL-AQH),lane,144));
            }
            #pragma unroll
            for (int nt=0;nt<2;++nt){
                uint32_t kf[4];
                ldm4(kf, aB(kvb + (wn*32+nt*16)*144 + k0*2, lane, 144));
                #pragma unroll
                for (int mi=0;mi<2;++mi)
                    #pragma unroll
                    for (int n8=0;n8<2;++n8){
                        mma16816(sacc[mi][nt*2+n8], qh[mi], kf+n8*2);
                        mma16816(sacc[mi][nt*2+n8], ql[mi], kf+n8*2);
                    }
            }
        }
        // ---- exp + P (fp16 hi only) ----
        #pragma unroll
        for (int mi=0;mi<2;++mi)
            #pragma unroll
            for (int j=0;j<4;++j){
                float p0=__expf(sacc[mi][j][0]), p1=__expf(sacc[mi][j][1]);
                float p2=__expf(sacc[mi][j][2]), p3=__expf(sacc[mi][j][3]);
                lsum[mi*2] += p0+p1; lsum[mi*2+1] += p2+p3;
                int col = wn*32 + (j>>1)*16 + (j&1)*8 + tig*2;
                int row = wm*32 + mi*16 + g;
                *(uint32_t*)(sm+APH+row*272+col*2)     = pk2(p0,p1);
                *(uint32_t*)(sm+APH+(row+8)*272+col*2) = pk2(p2,p3);
            }
        __syncthreads();
        // ---- O += Ph (Vh+Vl) ----
        #pragma unroll
        for (int ks=0;ks<8;++ks){
            int k0=ks*16;
            uint32_t ph[2][4], vh[4], vl[4];
            #pragma unroll
            for (int mi=0;mi<2;++mi)
                ldm4(ph[mi], aA(sb + APH + (wm*32+mi*16)*272 + k0*2, lane, 272));
            uint32_t vb = kvb + 18432 + k0*144 + wn*32;
            ldm4t(vh, aA(vb,lane,144));
            ldm4t(vl, aA(vb+18432,lane,144));
            #pragma unroll
            for (int mi=0;mi<2;++mi)
                #pragma unroll
                for (int n8=0;n8<2;++n8){
                    mma16816(oacc[mi][n8], ph[mi], vh+n8*2);
                    mma16816(oacc[mi][n8], ph[mi], vl+n8*2);
                }
        }
        if (t<15){
            char* nb = sm + AKV0 + ((t+1)&1)*AKVSZ;
            #pragma unroll
            for (int i=0;i<6;++i){
                int lin=tid+i*512, plane=lin>>10, rem=lin&1023, row=rem>>3, c8h=(rem&7)*4;
                *(uint4*)(nb + plane*18432 + row*144 + c8h*4) = kv[i];
            }
        }
        __syncthreads();
    }
    // ---- row-sum reduction: tig lanes, then across the 4 wn warps ----
    #pragma unroll
    for (int i=0;i<4;++i){
        lsum[i] += __shfl_xor_sync(0xffffffffu, lsum[i], 1);
        lsum[i] += __shfl_xor_sync(0xffffffffu, lsum[i], 2);
    }
    float* lred = (float*)(sm + ALR);
    if (tig==0){
        #pragma unroll
        for (int i=0;i<4;++i){
            int row = wm*32 + (i>>1)*16 + (i&1)*8 + g;
            lred[wn*128 + row] = lsum[i];
        }
    }
    __syncthreads();
    float inv[4];
    #pragma unroll
    for (int i=0;i<4;++i){
        int row = wm*32 + (i>>1)*16 + (i&1)*8 + g;
        inv[i] = 1.f/(lred[row] + lred[128+row] + lred[256+row] + lred[384+row]);
    }
    float* og = out + ((size_t)b*SEQ + q0)*HDIM;
    #pragma unroll
    for (int mi=0;mi<2;++mi)
        #pragma unroll
        for (int n8=0;n8<2;++n8){
            int col = wn*16 + n8*8 + tig*2;
            int r = wm*32 + mi*16 + g;
            *(float2*)(og + (size_t)r*HDIM + col) =
                make_float2(oacc[mi][n8][0]*inv[mi*2], oacc[mi][n8][1]*inv[mi*2]);
            *(float2*)(og + (size_t)(r+8)*HDIM + col) =
                make_float2(oacc[mi][n8][2]*inv[mi*2+1], oacc[mi][n8][3]*inv[mi*2+1]);
        }
}

extern "C" void kernel_launch(void* const* d_in, const int* in_sizes, int n_in,
                              void* d_out, int out_size)
{
    const float* x  = (const float*)d_in[0];
    const float* Wk = (const float*)d_in[1];
    const float* Wq = (const float*)d_in[2];
    const float* Wv = (const float*)d_in[3];
    float* out = (float*)d_out;

    cudaFuncSetAttribute(proj_mma, cudaFuncAttributeMaxDynamicSharedMemorySize, PJ_SMEM);
    cudaFuncSetAttribute(attn_mma, cudaFuncAttributeMaxDynamicSharedMemorySize, AT_SMEM);

    proj_mma<<<BT/128, 512, PJ_SMEM>>>(x, Wk, Wq, Wv);
    attn_mma<<<dim3(SEQ/128, BATCH), 512, AT_SMEM>>>(out);
}

// round 10
// speedup vs baseline: 1.7942x; 1.5089x over previous
#include <cuda_runtime.h>
#include <cuda_fp16.h>
#include <cstdint>

#define BATCH 8
#define SEQ   2048
#define CDIM  1024
#define HDIM  64
#define BT    (BATCH*SEQ)

// fp16 planes (packed u32 pairs), written by proj, read by attn (all hi-only)
__device__ uint32_t g_q[BT*32];     // q pre-scaled by 1/32
__device__ uint32_t g_k[BT*32];
__device__ uint32_t g_v[BT*32];

// ---------------- helpers ----------------
__device__ __forceinline__ uint32_t smem_u32(const void* p){
    uint32_t a; asm("{ .reg .u64 t; cvta.to.shared.u64 t, %1; cvt.u32.u64 %0, t; }" : "=r"(a) : "l"(p)); return a;
}
__device__ __forceinline__ void ldm4(uint32_t* r, uint32_t a){
    asm volatile("ldmatrix.sync.aligned.m8n8.x4.shared.b16 {%0,%1,%2,%3},[%4];"
        : "=r"(r[0]),"=r"(r[1]),"=r"(r[2]),"=r"(r[3]) : "r"(a));
}
__device__ __forceinline__ void ldm4t(uint32_t* r, uint32_t a){
    asm volatile("ldmatrix.sync.aligned.m8n8.x4.trans.shared.b16 {%0,%1,%2,%3},[%4];"
        : "=r"(r[0]),"=r"(r[1]),"=r"(r[2]),"=r"(r[3]) : "r"(a));
}
__device__ __forceinline__ void mma16816(float* d, const uint32_t* a, const uint32_t* b){
    asm volatile("mma.sync.aligned.m16n8k16.row.col.f32.f16.f16.f32 "
        "{%0,%1,%2,%3},{%4,%5,%6,%7},{%8,%9},{%0,%1,%2,%3};"
        : "+f"(d[0]),"+f"(d[1]),"+f"(d[2]),"+f"(d[3])
        : "r"(a[0]),"r"(a[1]),"r"(a[2]),"r"(a[3]),"r"(b[0]),"r"(b[1]));
}
__device__ __forceinline__ uint32_t pk2(float x, float y){
    __half2 t = __floats2half2_rn(x, y); return *(uint32_t*)&t;
}
__device__ __forceinline__ uint32_t aA(uint32_t base, int lane, int SB){
    return base + (uint32_t)((lane&15)*SB + (lane>>4)*16);
}
__device__ __forceinline__ uint32_t aB(uint32_t base, int lane, int SB){
    return base + (uint32_t)(((((lane>>4)&1)<<3) + (lane&7))*SB + ((lane>>3)&1)*16);
}

// ---------------- kernel 1: fused QKV projection (single-term, double-buffered) --------
// 512 thr, 16 warps (wm 0..3 x wn 0..3). M=128 rows, N=192. K chunks of 64.
// out = xh * Wh (all fp16 hi). In-CTA W f32->f16 convert (W is L2-resident).
#define PX  0
#define PB  18432            // 64 rows x 400B (192 f16 + pad)
#define PBUF 44032
#define PJ_SMEM 88064
__global__ __launch_bounds__(512,1) void proj_mma(
    const float* __restrict__ x, const float* __restrict__ Wk,
    const float* __restrict__ Wq, const float* __restrict__ Wv)
{
    extern __shared__ char sm[];
    const uint32_t sb = smem_u32(sm);
    const int tid=threadIdx.x, lane=tid&31, wid=tid>>5;
    const int wm=wid>>2, wn=wid&3, g=lane>>2, tig=lane&3;
    const int m0 = blockIdx.x*128;
    const float* Ws[3] = {Wk, Wq, Wv};

    float4 xr[4], wr[6];
    #pragma unroll
    for (int i=0;i<4;++i){ int lin=tid+i*512, row=lin>>4, c4=(lin&15)*4;
        xr[i] = *(const float4*)(x + (size_t)(m0+row)*CDIM + c4); }
    #pragma unroll
    for (int i=0;i<6;++i){ int lin=tid+i*512, row=lin/48, c4=(lin-row*48)*4;
        wr[i] = *(const float4*)(Ws[c4>>6] + (size_t)row*HDIM + (c4&63)); }
    #pragma unroll
    for (int i=0;i<4;++i){ int lin=tid+i*512, row=lin>>4, c4=(lin&15)*4;
        *(uint2*)(sm + PX + row*144 + c4*2) = make_uint2(pk2(xr[i].x,xr[i].y), pk2(xr[i].z,xr[i].w)); }
    #pragma unroll
    for (int i=0;i<6;++i){ int lin=tid+i*512, row=lin/48, c4=(lin-row*48)*4;
        *(uint2*)(sm + PB + row*400 + c4*2) = make_uint2(pk2(wr[i].x,wr[i].y), pk2(wr[i].z,wr[i].w)); }
    __syncthreads();

    float acc[2][3][2][4] = {};
    for (int c=0;c<16;++c){
        uint32_t pbu = sb + (c&1)*PBUF;
        if (c<15){
            #pragma unroll
            for (int i=0;i<4;++i){ int lin=tid+i*512, row=lin>>4, c4=(lin&15)*4;
                xr[i] = *(const float4*)(x + (size_t)(m0+row)*CDIM + (c+1)*64 + c4); }
            #pragma unroll
            for (int i=0;i<6;++i){ int lin=tid+i*512, row=lin/48, c4=(lin-row*48)*4;
                wr[i] = *(const float4*)(Ws[c4>>6] + (size_t)((c+1)*64+row)*HDIM + (c4&63)); }
        }
        #pragma unroll
        for (int ks=0;ks<4;++ks){
            int k0 = ks*16;
            uint32_t ah[2][4];
            #pragma unroll
            for (int mi=0;mi<2;++mi)
                ldm4(ah[mi], aA(pbu + PX + (wm*32+mi*16)*144 + k0*2, lane, 144));
            #pragma unroll
            for (int nt=0;nt<3;++nt){
                uint32_t bh[4];
                ldm4t(bh, aA(pbu + PB + k0*400 + (wn+nt*4)*32, lane, 400));
                #pragma unroll
                for (int mi=0;mi<2;++mi)
                    #pragma unroll
                    for (int n8=0;n8<2;++n8)
                        mma16816(acc[mi][nt][n8], ah[mi], bh+n8*2);
            }
        }
        if (c<15){
            char* nb = sm + ((c+1)&1)*PBUF;
            #pragma unroll
            for (int i=0;i<4;++i){ int lin=tid+i*512, row=lin>>4, c4=(lin&15)*4;
                *(uint2*)(nb + PX + row*144 + c4*2) = make_uint2(pk2(xr[i].x,xr[i].y), pk2(xr[i].z,xr[i].w)); }
            #pragma unroll
            for (int i=0;i<6;++i){ int lin=tid+i*512, row=lin/48, c4=(lin-row*48)*4;
                *(uint2*)(nb + PB + row*400 + c4*2) = make_uint2(pk2(wr[i].x,wr[i].y), pk2(wr[i].z,wr[i].w)); }
        }
        __syncthreads();
    }
    #pragma unroll
    for (int mi=0;mi<2;++mi)
        #pragma unroll
        for (int nt=0;nt<3;++nt)
            #pragma unroll
            for (int n8=0;n8<2;++n8){
                int ncol = (wn+nt*4)*16 + n8*8 + tig*2;
                int cc = ncol&63;
                int r0 = m0 + wm*32 + mi*16 + g;
                float* a = acc[mi][nt][n8];
                uint32_t* dst = (nt==0)? g_k : (nt==1)? g_q : g_v;
                float s = (nt==1)? 0.03125f : 1.f;
                dst[((size_t)r0*64+cc)>>1]     = pk2(a[0]*s, a[1]*s);
                dst[((size_t)(r0+8)*64+cc)>>1] = pk2(a[2]*s, a[3]*s);
            }
}

// ---------------- kernel 2: attention (single-term S and PV, Q frags hoisted) ----------
// 512 thr, 16 warps. 2 syncs/iter, double-buffered KV.
#define AQ  0
#define AKV0 18432           // per buffer: K +0 | V +18432 (36864 B); two buffers
#define AKVSZ 36864
#define AP  92160            // 128 x 272B
#define ALR 126976
#define AT_SMEM 129024
__global__ __launch_bounds__(512,1) void attn_mma(float* __restrict__ out){
    extern __shared__ char sm[];
    const uint32_t sb = smem_u32(sm);
    const int tid=threadIdx.x, lane=tid&31, wid=tid>>5;
    const int wm=wid>>2, wn=wid&3, g=lane>>2, tig=lane&3;
    const int b=blockIdx.y, q0=blockIdx.x*128;

    // stage Q
    #pragma unroll
    for (int i=0;i<2;++i){
        int lin=tid+i*512, row=lin>>3, c8h=(lin&7)*4;
        *(uint4*)(sm + AQ + row*144 + c8h*4) =
            *(const uint4*)(g_q + ((size_t)(b*SEQ+q0)+row)*32 + c8h);
    }
    // load + stage KV tile 0 into buf0
    uint4 kv[4];
    #pragma unroll
    for (int i=0;i<4;++i){
        int lin=tid+i*512, plane=lin>>10, rem=lin&1023, row=rem>>3, c8h=(rem&7)*4;
        const uint32_t* gp = plane? g_v : g_k;
        kv[i] = *(const uint4*)(gp + ((size_t)(b*SEQ)+row)*32 + c8h);
    }
    #pragma unroll
    for (int i=0;i<4;++i){
        int lin=tid+i*512, plane=lin>>10, rem=lin&1023, row=rem>>3, c8h=(rem&7)*4;
        *(uint4*)(sm + AKV0 + plane*18432 + row*144 + c8h*4) = kv[i];
    }
    __syncthreads();

    // hoist Q fragments (invariant over t)
    uint32_t qf[4][2][4];
    #pragma unroll
    for (int ks=0;ks<4;++ks)
        #pragma unroll
        for (int mi=0;mi<2;++mi)
            ldm4(qf[ks][mi], aA(sb + AQ + (wm*32+mi*16)*144 + ks*32, lane, 144));

    float oacc[2][2][4] = {};
    float lsum[4] = {};
    for (int t=0;t<16;++t){
        uint32_t kvb = sb + AKV0 + (t&1)*AKVSZ;
        if (t<15){
            #pragma unroll
            for (int i=0;i<4;++i){
                int lin=tid+i*512, plane=lin>>10, rem=lin&1023, row=rem>>3, c8h=(rem&7)*4;
                const uint32_t* gp = plane? g_v : g_k;
                kv[i] = *(const uint4*)(gp + ((size_t)(b*SEQ)+(t+1)*128+row)*32 + c8h);
            }
        }
        // ---- S = Q K^T (single term) ----
        float sacc[2][4][4] = {};
        #pragma unroll
        for (int ks=0;ks<4;++ks){
            int k0=ks*16;
            #pragma unroll
            for (int nt=0;nt<2;++nt){
                uint32_t kf[4];
                ldm4(kf, aB(kvb + (wn*32+nt*16)*144 + k0*2, lane, 144));
                #pragma unroll
                for (int mi=0;mi<2;++mi)
                    #pragma unroll
                    for (int n8=0;n8<2;++n8)
                        mma16816(sacc[mi][nt*2+n8], qf[ks][mi], kf+n8*2);
            }
        }
        // ---- exp + P (fp16) ----
        #pragma unroll
        for (int mi=0;mi<2;++mi)
            #pragma unroll
            for (int j=0;j<4;++j){
                float p0=__expf(sacc[mi][j][0]), p1=__expf(sacc[mi][j][1]);
                float p2=__expf(sacc[mi][j][2]), p3=__expf(sacc[mi][j][3]);
                lsum[mi*2] += p0+p1; lsum[mi*2+1] += p2+p3;
                int col = wn*32 + (j>>1)*16 + (j&1)*8 + tig*2;
                int row = wm*32 + mi*16 + g;
                *(uint32_t*)(sm+AP+row*272+col*2)     = pk2(p0,p1);
                *(uint32_t*)(sm+AP+(row+8)*272+col*2) = pk2(p2,p3);
            }
        __syncthreads();
        // ---- O += P V ----
        #pragma unroll
        for (int ks=0;ks<8;++ks){
            int k0=ks*16;
            uint32_t ph[2][4], vh[4];
            #pragma unroll
            for (int mi=0;mi<2;++mi)
                ldm4(ph[mi], aA(sb + AP + (wm*32+mi*16)*272 + k0*2, lane, 272));
            ldm4t(vh, aA(kvb + 18432 + k0*144 + wn*32, lane, 144));
            #pragma unroll
            for (int mi=0;mi<2;++mi)
                #pragma unroll
                for (int n8=0;n8<2;++n8)
                    mma16816(oacc[mi][n8], ph[mi], vh+n8*2);
        }
        if (t<15){
            char* nb = sm + AKV0 + ((t+1)&1)*AKVSZ;
            #pragma unroll
            for (int i=0;i<4;++i){
                int lin=tid+i*512, plane=lin>>10, rem=lin&1023, row=rem>>3, c8h=(rem&7)*4;
                *(uint4*)(nb + plane*18432 + row*144 + c8h*4) = kv[i];
            }
        }
        __syncthreads();
    }
    // ---- row-sum reduction: tig lanes, then across the 4 wn warps ----
    #pragma unroll
    for (int i=0;i<4;++i){
        lsum[i] += __shfl_xor_sync(0xffffffffu, lsum[i], 1);
        lsum[i] += __shfl_xor_sync(0xffffffffu, lsum[i], 2);
    }
    float* lred = (float*)(sm + ALR);
    if (tig==0){
        #pragma unroll
        for (int i=0;i<4;++i){
            int row = wm*32 + (i>>1)*16 + (i&1)*8 + g;
            lred[wn*128 + row] = lsum[i];
        }
    }
    __syncthreads();
    float inv[4];
    #pragma unroll
    for (int i=0;i<4;++i){
        int row = wm*32 + (i>>1)*16 + (i&1)*8 + g;
        inv[i] = 1.f/(lred[row] + lred[128+row] + lred[256+row] + lred[384+row]);
    }
    float* og = out + ((size_t)b*SEQ + q0)*HDIM;
    #pragma unroll
    for (int mi=0;mi<2;++mi)
        #pragma unroll
        for (int n8=0;n8<2;++n8){
            int col = wn*16 + n8*8 + tig*2;
            int r = wm*32 + mi*16 + g;
            *(float2*)(og + (size_t)r*HDIM + col) =
                make_float2(oacc[mi][n8][0]*inv[mi*2], oacc[mi][n8][1]*inv[mi*2]);
            *(float2*)(og + (size_t)(r+8)*HDIM + col) =
                make_float2(oacc[mi][n8][2]*inv[mi*2+1], oacc[mi][n8][3]*inv[mi*2+1]);
        }
}

extern "C" void kernel_launch(void* const* d_in, const int* in_sizes, int n_in,
                              void* d_out, int out_size)
{
    const float* x  = (const float*)d_in[0];
    const float* Wk = (const float*)d_in[1];
    const float* Wq = (const float*)d_in[2];
    const float* Wv = (const float*)d_in[3];
    float* out = (float*)d_out;

    cudaFuncSetAttribute(proj_mma, cudaFuncAttributeMaxDynamicSharedMemorySize, PJ_SMEM);
    cudaFuncSetAttribute(attn_mma, cudaFuncAttributeMaxDynamicSharedMemorySize, AT_SMEM);

    proj_mma<<<BT/128, 512, PJ_SMEM>>>(x, Wk, Wq, Wv);
    attn_mma<<<dim3(SEQ/128, BATCH), 512, AT_SMEM>>>(out);
}

// round 11
// speedup vs baseline: 2.0195x; 1.1256x over previous
#include <cuda_runtime.h>
#include <cuda_fp16.h>
#include <cstdint>

#define BATCH 8
#define SEQ   2048
#define CDIM  1024
#define HDIM  64
#define BT    (BATCH*SEQ)

// fp16 planes (packed u32 pairs), written by proj, read by attn (all hi-only)
__device__ uint32_t g_q[BT*32];     // q pre-scaled by log2(e)/32
__device__ uint32_t g_k[BT*32];
__device__ uint32_t g_v[BT*32];

// ---------------- helpers ----------------
__device__ __forceinline__ uint32_t smem_u32(const void* p){
    uint32_t a; asm("{ .reg .u64 t; cvta.to.shared.u64 t, %1; cvt.u32.u64 %0, t; }" : "=r"(a) : "l"(p)); return a;
}
__device__ __forceinline__ void ldm4(uint32_t* r, uint32_t a){
    asm volatile("ldmatrix.sync.aligned.m8n8.x4.shared.b16 {%0,%1,%2,%3},[%4];"
        : "=r"(r[0]),"=r"(r[1]),"=r"(r[2]),"=r"(r[3]) : "r"(a));
}
__device__ __forceinline__ void ldm4t(uint32_t* r, uint32_t a){
    asm volatile("ldmatrix.sync.aligned.m8n8.x4.trans.shared.b16 {%0,%1,%2,%3},[%4];"
        : "=r"(r[0]),"=r"(r[1]),"=r"(r[2]),"=r"(r[3]) : "r"(a));
}
__device__ __forceinline__ void mma16816(float* d, const uint32_t* a, const uint32_t* b){
    asm volatile("mma.sync.aligned.m16n8k16.row.col.f32.f16.f16.f32 "
        "{%0,%1,%2,%3},{%4,%5,%6,%7},{%8,%9},{%0,%1,%2,%3};"
        : "+f"(d[0]),"+f"(d[1]),"+f"(d[2]),"+f"(d[3])
        : "r"(a[0]),"r"(a[1]),"r"(a[2]),"r"(a[3]),"r"(b[0]),"r"(b[1]));
}
__device__ __forceinline__ uint32_t pk2(float x, float y){
    __half2 t = __floats2half2_rn(x, y); return *(uint32_t*)&t;
}
__device__ __forceinline__ uint32_t aA(uint32_t base, int lane, int SB){
    return base + (uint32_t)((lane&15)*SB + (lane>>4)*16);
}
__device__ __forceinline__ uint32_t aB(uint32_t base, int lane, int SB){
    return base + (uint32_t)(((((lane>>4)&1)<<3) + (lane&7))*SB + ((lane>>3)&1)*16);
}

// ---------------- kernel 1: fused QKV projection (single-term, double-buffered) --------
#define PX  0
#define PB  18432            // 64 rows x 400B (192 f16 + pad)
#define PBUF 44032
#define PJ_SMEM 88064
__global__ __launch_bounds__(512,1) void proj_mma(
    const float* __restrict__ x, const float* __restrict__ Wk,
    const float* __restrict__ Wq, const float* __restrict__ Wv)
{
    extern __shared__ char sm[];
    const uint32_t sb = smem_u32(sm);
    const int tid=threadIdx.x, lane=tid&31, wid=tid>>5;
    const int wm=wid>>2, wn=wid&3, g=lane>>2, tig=lane&3;
    const int m0 = blockIdx.x*128;
    const float* Ws[3] = {Wk, Wq, Wv};

    float4 xr[4], wr[6];
    #pragma unroll
    for (int i=0;i<4;++i){ int lin=tid+i*512, row=lin>>4, c4=(lin&15)*4;
        xr[i] = *(const float4*)(x + (size_t)(m0+row)*CDIM + c4); }
    #pragma unroll
    for (int i=0;i<6;++i){ int lin=tid+i*512, row=lin/48, c4=(lin-row*48)*4;
        wr[i] = *(const float4*)(Ws[c4>>6] + (size_t)row*HDIM + (c4&63)); }
    #pragma unroll
    for (int i=0;i<4;++i){ int lin=tid+i*512, row=lin>>4, c4=(lin&15)*4;
        *(uint2*)(sm + PX + row*144 + c4*2) = make_uint2(pk2(xr[i].x,xr[i].y), pk2(xr[i].z,xr[i].w)); }
    #pragma unroll
    for (int i=0;i<6;++i){ int lin=tid+i*512, row=lin/48, c4=(lin-row*48)*4;
        *(uint2*)(sm + PB + row*400 + c4*2) = make_uint2(pk2(wr[i].x,wr[i].y), pk2(wr[i].z,wr[i].w)); }
    __syncthreads();

    float acc[2][3][2][4] = {};
    for (int c=0;c<16;++c){
        uint32_t pbu = sb + (c&1)*PBUF;
        if (c<15){
            #pragma unroll
            for (int i=0;i<4;++i){ int lin=tid+i*512, row=lin>>4, c4=(lin&15)*4;
                xr[i] = *(const float4*)(x + (size_t)(m0+row)*CDIM + (c+1)*64 + c4); }
            #pragma unroll
            for (int i=0;i<6;++i){ int lin=tid+i*512, row=lin/48, c4=(lin-row*48)*4;
                wr[i] = *(const float4*)(Ws[c4>>6] + (size_t)((c+1)*64+row)*HDIM + (c4&63)); }
        }
        #pragma unroll
        for (int ks=0;ks<4;++ks){
            int k0 = ks*16;
            uint32_t ah[2][4];
            #pragma unroll
            for (int mi=0;mi<2;++mi)
                ldm4(ah[mi], aA(pbu + PX + (wm*32+mi*16)*144 + k0*2, lane, 144));
            #pragma unroll
            for (int nt=0;nt<3;++nt){
                uint32_t bh[4];
                ldm4t(bh, aA(pbu + PB + k0*400 + (wn+nt*4)*32, lane, 400));
                #pragma unroll
                for (int mi=0;mi<2;++mi)
                    #pragma unroll
                    for (int n8=0;n8<2;++n8)
                        mma16816(acc[mi][nt][n8], ah[mi], bh+n8*2);
            }
        }
        if (c<15){
            char* nb = sm + ((c+1)&1)*PBUF;
            #pragma unroll
            for (int i=0;i<4;++i){ int lin=tid+i*512, row=lin>>4, c4=(lin&15)*4;
                *(uint2*)(nb + PX + row*144 + c4*2) = make_uint2(pk2(xr[i].x,xr[i].y), pk2(xr[i].z,xr[i].w)); }
            #pragma unroll
            for (int i=0;i<6;++i){ int lin=tid+i*512, row=lin/48, c4=(lin-row*48)*4;
                *(uint2*)(nb + PB + row*400 + c4*2) = make_uint2(pk2(wr[i].x,wr[i].y), pk2(wr[i].z,wr[i].w)); }
        }
        __syncthreads();
    }
    #pragma unroll
    for (int mi=0;mi<2;++mi)
        #pragma unroll
        for (int nt=0;nt<3;++nt)
            #pragma unroll
            for (int n8=0;n8<2;++n8){
                int ncol = (wn+nt*4)*16 + n8*8 + tig*2;
                int cc = ncol&63;
                int r0 = m0 + wm*32 + mi*16 + g;
                float* a = acc[mi][nt][n8];
                uint32_t* dst = (nt==0)? g_k : (nt==1)? g_q : g_v;
                float s = (nt==1)? 0.03125f*1.44269504f : 1.f;   // fold log2(e) for exp2
                dst[((size_t)r0*64+cc)>>1]     = pk2(a[0]*s, a[1]*s);
                dst[((size_t)(r0+8)*64+cc)>>1] = pk2(a[2]*s, a[3]*s);
            }
}

// ---------------- kernel 2: attention (register-resident P, 8m x 2n warps) -------------
// 512 thr. Warp = 16 q-rows x 64 keys. S acc -> exp2 -> packed A-frag in regs -> PV.
// 1 sync/iter. 2-way O/lsum cross-warp reduce at end.
#define AQ    0
#define AKV0  18432          // per buffer: K +0 | V +18432 (36864 B); two buffers
#define AKVSZ 36864
#define AOP   92160          // partial O: 8 x 16 x 64 f32 = 32768
#define ALP   124928         // partial lsum: 128 f32
#define AT_SMEM 125440
__global__ __launch_bounds__(512,1) void attn_mma(float* __restrict__ out){
    extern __shared__ char sm[];
    const uint32_t sb = smem_u32(sm);
    const int tid=threadIdx.x, lane=tid&31, wid=tid>>5;
    const int wm=wid>>1, wn=wid&1, g=lane>>2, tig=lane&3;
    const int b=blockIdx.y, q0=blockIdx.x*128;

    // stage Q
    #pragma unroll
    for (int i=0;i<2;++i){
        int lin=tid+i*512, row=lin>>3, c8h=(lin&7)*4;
        *(uint4*)(sm + AQ + row*144 + c8h*4) =
            *(const uint4*)(g_q + ((size_t)(b*SEQ+q0)+row)*32 + c8h);
    }
    // load + stage KV tile 0 into buf0
    uint4 kv[4];
    #pragma unroll
    for (int i=0;i<4;++i){
        int lin=tid+i*512, plane=lin>>10, rem=lin&1023, row=rem>>3, c8h=(rem&7)*4;
        const uint32_t* gp = plane? g_v : g_k;
        kv[i] = *(const uint4*)(gp + ((size_t)(b*SEQ)+row)*32 + c8h);
    }
    #pragma unroll
    for (int i=0;i<4;++i){
        int lin=tid+i*512, plane=lin>>10, rem=lin&1023, row=rem>>3, c8h=(rem&7)*4;
        *(uint4*)(sm + AKV0 + plane*18432 + row*144 + c8h*4) = kv[i];
    }
    __syncthreads();

    // hoist Q fragments (warp rows wm*16..+16, invariant over t)
    uint32_t qf[4][4];
    #pragma unroll
    for (int ks=0;ks<4;++ks)
        ldm4(qf[ks], aA(sb + AQ + (wm*16)*144 + ks*32, lane, 144));

    float oacc[8][4] = {};
    float lsum[2] = {};
    for (int t=0;t<16;++t){
        uint32_t kvb = sb + AKV0 + (t&1)*AKVSZ;
        if (t<15){
            #pragma unroll
            for (int i=0;i<4;++i){
                int lin=tid+i*512, plane=lin>>10, rem=lin&1023, row=rem>>3, c8h=(rem&7)*4;
                const uint32_t* gp = plane? g_v : g_k;
                kv[i] = *(const uint4*)(gp + ((size_t)(b*SEQ)+(t+1)*128+row)*32 + c8h);
            }
        }
        // ---- S = Q K^T over warp's 64 keys ----
        float sacc[8][4] = {};
        #pragma unroll
        for (int ks=0;ks<4;++ks){
            #pragma unroll
            for (int nt=0;nt<4;++nt){
                uint32_t kf[4];
                ldm4(kf, aB(kvb + (wn*64+nt*16)*144 + ks*32, lane, 144));
                mma16816(sacc[nt*2+0], qf[ks], kf+0);
                mma16816(sacc[nt*2+1], qf[ks], kf+2);
            }
        }
        // ---- exp2 + pack P directly into A-fragments (registers only) ----
        uint32_t pa[4][4];
        #pragma unroll
        for (int j=0;j<4;++j){
            float e0=exp2f(sacc[2*j][0]),   e1=exp2f(sacc[2*j][1]);
            float e2=exp2f(sacc[2*j][2]),   e3=exp2f(sacc[2*j][3]);
            float e4=exp2f(sacc[2*j+1][0]), e5=exp2f(sacc[2*j+1][1]);
            float e6=exp2f(sacc[2*j+1][2]), e7=exp2f(sacc[2*j+1][3]);
            lsum[0] += (e0+e1)+(e4+e5);
            lsum[1] += (e2+e3)+(e6+e7);
            pa[j][0]=pk2(e0,e1); pa[j][1]=pk2(e2,e3);
            pa[j][2]=pk2(e4,e5); pa[j][3]=pk2(e6,e7);
        }
        // ---- O_partial += P V (warp's 64 keys, full 64 cols) ----
        #pragma unroll
        for (int ks=0;ks<4;++ks){
            #pragma unroll
            for (int nc=0;nc<4;++nc){
                uint32_t vh[4];
                ldm4t(vh, aA(kvb + 18432 + (wn*64+ks*16)*144 + nc*32, lane, 144));
                mma16816(oacc[nc*2+0], pa[ks], vh+0);
                mma16816(oacc[nc*2+1], pa[ks], vh+2);
            }
        }
        if (t<15){
            char* nb = sm + AKV0 + ((t+1)&1)*AKVSZ;
            #pragma unroll
            for (int i=0;i<4;++i){
                int lin=tid+i*512, plane=lin>>10, rem=lin&1023, row=rem>>3, c8h=(rem&7)*4;
                *(uint4*)(nb + plane*18432 + row*144 + c8h*4) = kv[i];
            }
        }
        __syncthreads();
    }
    // ---- reduce lsum over tig lanes (full 64-key sums per row) ----
    #pragma unroll
    for (int i=0;i<2;++i){
        lsum[i] += __shfl_xor_sync(0xffffffffu, lsum[i], 1);
        lsum[i] += __shfl_xor_sync(0xffffffffu, lsum[i], 2);
    }
    // ---- cross-warp (wn pair) O + lsum reduction ----
    float* op = (float*)(sm + AOP) + wm*16*64;
    float* lp = (float*)(sm + ALP);
    if (wn==1){
        #pragma unroll
        for (int n8=0;n8<8;++n8){
            int col = n8*8 + tig*2;
            *(float2*)(op + g*64 + col)     = make_float2(oacc[n8][0], oacc[n8][1]);
            *(float2*)(op + (g+8)*64 + col) = make_float2(oacc[n8][2], oacc[n8][3]);
        }
        if (tig==0){ lp[wm*16+g] = lsum[0]; lp[wm*16+g+8] = lsum[1]; }
    }
    __syncthreads();
    if (wn==0){
        float inv0 = 1.f/(lsum[0] + lp[wm*16+g]);
        float inv1 = 1.f/(lsum[1] + lp[wm*16+g+8]);
        float* og = out + ((size_t)b*SEQ + q0 + wm*16)*HDIM;
        #pragma unroll
        for (int n8=0;n8<8;++n8){
            int col = n8*8 + tig*2;
            float2 p0 = *(float2*)(op + g*64 + col);
            float2 p1 = *(float2*)(op + (g+8)*64 + col);
            *(float2*)(og + (size_t)g*HDIM + col) =
                make_float2((oacc[n8][0]+p0.x)*inv0, (oacc[n8][1]+p0.y)*inv0);
            *(float2*)(og + (size_t)(g+8)*HDIM + col) =
                make_float2((oacc[n8][2]+p1.x)*inv1, (oacc[n8][3]+p1.y)*inv1);
        }
    }
}

extern "C" void kernel_launch(void* const* d_in, const int* in_sizes, int n_in,
                              void* d_out, int out_size)
{
    const float* x  = (const float*)d_in[0];
    const float* Wk = (const float*)d_in[1];
    const float* Wq = (const float*)d_in[2];
    const float* Wv = (const float*)d_in[3];
    float* out = (float*)d_out;

    cudaFuncSetAttribute(proj_mma, cudaFuncAttributeMaxDynamicSharedMemorySize, PJ_SMEM);
    cudaFuncSetAttribute(attn_mma, cudaFuncAttributeMaxDynamicSharedMemorySize, AT_SMEM);

    proj_mma<<<BT/128, 512, PJ_SMEM>>>(x, Wk, Wq, Wv);
    attn_mma<<<dim3(SEQ/128, BATCH), 512, AT_SMEM>>>(out);
}